// round 16
// baseline (speedup 1.0000x reference)
#include <cuda_runtime.h>
#include <cuda_fp16.h>
#include <cstdint>

// Problem constants
#define DIMC   512
#define HEADSC 8
#define NTOK   64          // tokens per window (8x8)
#define BWIN   2048        // number of windows (32*64)
#define MROWS  (BWIN*NTOK) // 131072
#define PER_LAT 225
#define NMB    (MROWS/64)  // 2048 m-blocks of 64 rows

// ---------------- scratch (static device memory; allocation is forbidden) ----
__device__ __half g_q [BWIN*HEADSC*NTOK*64]; // [B][H][N][D] fp16, q pre-scaled by 0.125
__device__ __half g_k [BWIN*HEADSC*NTOK*64];
__device__ __half g_v [BWIN*HEADSC*NTOK*64];
__device__ __half g_ao[(size_t)MROWS*DIMC];  // attention output fp16, [M,512]
__device__ __half g_xh[(size_t)MROWS*DIMC];  // x rounded to fp16
__device__ __half g_wq[3*DIMC*DIMC];         // w_qkv fp16
__device__ __half g_wp[DIMC*DIMC];           // w_proj fp16

// ---------------- helpers ----------------------------------------------------
__device__ __forceinline__ void mma16(float* c, const uint32_t* a, const uint32_t* b){
    asm volatile(
      "mma.sync.aligned.m16n8k16.row.col.f32.f16.f16.f32 "
      "{%0,%1,%2,%3}, {%4,%5,%6,%7}, {%8,%9}, {%0,%1,%2,%3};"
      : "+f"(c[0]), "+f"(c[1]), "+f"(c[2]), "+f"(c[3])
      : "r"(a[0]), "r"(a[1]), "r"(a[2]), "r"(a[3]), "r"(b[0]), "r"(b[1]));
}
__device__ __forceinline__ void ldm_x4(uint32_t* r, uint32_t addr){
    asm volatile("ldmatrix.sync.aligned.m8n8.x4.shared.b16 {%0,%1,%2,%3}, [%4];"
                 : "=r"(r[0]), "=r"(r[1]), "=r"(r[2]), "=r"(r[3]) : "r"(addr));
}
__device__ __forceinline__ void ldm_x4t(uint32_t* r, uint32_t addr){
    asm volatile("ldmatrix.sync.aligned.m8n8.x4.trans.shared.b16 {%0,%1,%2,%3}, [%4];"
                 : "=r"(r[0]), "=r"(r[1]), "=r"(r[2]), "=r"(r[3]) : "r"(addr));
}
__device__ __forceinline__ void cp16(uint32_t dst, const void* src){
    asm volatile("cp.async.cg.shared.global [%0], [%1], 16;\n" :: "r"(dst), "l"(src));
}
__device__ __forceinline__ void cp_commit(){ asm volatile("cp.async.commit_group;\n" ::); }
__device__ __forceinline__ void cp_wait1(){ asm volatile("cp.async.wait_group 1;\n" ::); }
__device__ __forceinline__ void nbar(int id){ asm volatile("bar.sync %0, 128;" :: "r"(id) : "memory"); }
__device__ __forceinline__ uint32_t h2u(half2 h){ return *reinterpret_cast<uint32_t*>(&h); }

// ---------------- merged pre-round pass: fp16_rn of x, w_qkv, w_proj ---------
__global__ void round_all(const float* __restrict__ x,    __half* __restrict__ xh,
                          const float* __restrict__ wq,   __half* __restrict__ wqh,
                          const float* __restrict__ wp,   __half* __restrict__ wph)
{
    const int nx = (int)((size_t)MROWS*DIMC/4);
    const int nq = 3*DIMC*DIMC/4;
    const int np = DIMC*DIMC/4;
    const int total = nx + nq + np;
    int i = blockIdx.x * blockDim.x + threadIdx.x;
    const int stride = gridDim.x * blockDim.x;
    for (; i < total; i += stride){
        const float* s; __half* d; int k;
        if (i < nx){ s = x; d = xh; k = i; }
        else if (i < nx + nq){ s = wq; d = wqh; k = i - nx; }
        else { s = wp; d = wph; k = i - nx - nq; }
        float4 v = ((const float4*)s)[k];
        half2 h0 = __floats2half2_rn(v.x, v.y);
        half2 h1 = __floats2half2_rn(v.z, v.w);
        ((uint2*)d)[k] = make_uint2(h2u(h0), h2u(h1));
    }
}

// ---------------- persistent-B fp16 GEMM -------------------------------------
// C[M,N] = A[M,K] * W[N,K]^T + bias[N], K=512.
// One CTA per (n-panel, SM-slot): keeps B[128 n][512 k] fp16 (128 KB, swizzled)
// resident in SMEM; 8 warps split into 2 independent 4-warp groups (named
// barriers 1/2), each streaming 64-row m-blocks with double-buffered A stages
// (8 KB each). Swizzle: 16B chunk c at ((c ^ (row&7)) low-3-bit XOR).
// MODE 0: epilogue -> q/k/v fp16 scatter (q scaled); MODE 1: -> f32 out.
#define B_BYTES (128*1024)              // 128 rows x 1024 B
#define A_STG   8192                    // 64 rows x 128 B
#define GSMEM_BYTES (B_BYTES + 4*A_STG) // 163840

template<int MODE>
__global__ void __launch_bounds__(256)
gemm_f16(const __half* __restrict__ A, const __half* __restrict__ W,
         const float* __restrict__ bias, float* __restrict__ out)
{
    extern __shared__ uint8_t smem[];
    const uint32_t sbase = (uint32_t)__cvta_generic_to_shared(smem);

    const int tid  = threadIdx.x;
    const int lane = tid & 31;
    const int wid  = tid >> 5;           // 0..7
    const int gid  = wid >> 2;           // group 0/1
    const int tg   = tid & 127;          // tid within group
    const int gwid = wid & 3;            // warp within group
    const int n0   = blockIdx.x * 128;
    const int g    = lane >> 2;
    const int t4   = lane & 3;
    const int wm   = (gwid & 1) * 32;    // M within group tile: 2 warps x 32
    const int wn   = (gwid >> 1) * 64;   // N: 2 warps x 64

    const __half* Wg = W + (size_t)n0 * 512;

    // fragment lane geometry (low 3 bits of row == lane&7)
    const int l7   = lane & 7;
    const int ahi  = (lane >> 4) & 1;
    const int arow = wm + l7 + ((lane >> 3) & 1) * 8;        // + i*16
    const int bhi  = (lane >> 3) & 1;
    const int brow = wn + l7 + ((lane >> 4) & 1) * 8;        // + j2*16

    const uint32_t Abase  = sbase + B_BYTES + (uint32_t)gid * (2*A_STG);
    const uint32_t arow_b = (uint32_t)arow * 128;

    // ---- load resident B panel (all 256 threads) ----
    #pragma unroll 4
    for (int i = 0; i < 32; i++){
        const int cb = i*256 + tid;          // 0..8191
        const int n  = cb >> 6;
        const int c  = cb & 63;
        cp16(sbase + (uint32_t)n*1024 + (uint32_t)((c ^ (n & 7)) << 4),
             Wg + (size_t)n*512 + c*8);
    }
    cp_commit();                              // FIFO: [B]

    // A stage loader for this group
    auto issueA = [&](int mb, int kt, int buf){
        const uint32_t so = Abase + (uint32_t)buf * A_STG;
        const __half* src = A + ((size_t)mb*64)*512 + kt*64;
        #pragma unroll
        for (int p=0;p<4;p++){
            const int c   = p*128 + tg;      // 0..511
            const int row = c >> 3;
            const int cc  = c & 7;
            cp16(so + (uint32_t)row*128 + (uint32_t)((cc ^ (row & 7)) << 4),
                 src + (size_t)row*512 + cc*8);
        }
        cp_commit();
    };

    const int mb0 = blockIdx.y * 2 + gid;     // first m-block for this group
    if (mb0 < NMB) issueA(mb0, 0, 0);         // FIFO: [B, A0]
    else           cp_commit();
    cp_wait1();                               // B complete
    __syncthreads();                          // B visible CTA-wide (only CTA-wide bar)

    const int bar = gid + 1;
    int buf = 0;

    for (int mb = mb0; mb < NMB; mb += 296){
        float acc[2][8][4];
        #pragma unroll
        for (int i=0;i<2;i++)
          #pragma unroll
          for (int j=0;j<8;j++)
            #pragma unroll
            for (int e=0;e<4;e++) acc[i][j][e] = 0.f;

        for (int kt = 0; kt < 8; kt++){
            nbar(bar);                        // group done computing other buffer
            int nkt = kt + 1, nmb = mb;
            if (nkt == 8){ nkt = 0; nmb = mb + 296; }
            if (nmb < NMB) issueA(nmb, nkt, buf ^ 1);
            else           cp_commit();       // uniform FIFO
            cp_wait1();                       // current ktile resident
            nbar(bar);                        // visible to whole group

            const uint32_t sA = Abase + (uint32_t)buf * A_STG;
            #pragma unroll
            for (int ks=0; ks<4; ks++){
                uint32_t af[2][4];
                #pragma unroll
                for (int i=0;i<2;i++)
                    ldm_x4(af[i], sA + arow_b + (uint32_t)(i*16*128)
                                 + (uint32_t)(((ks*2 + ahi) ^ l7) << 4));
                #pragma unroll
                for (int j2=0;j2<4;j2++){
                    uint32_t bq[4];
                    ldm_x4(bq, sbase + (uint32_t)((brow + j2*16) * 1024)
                              + (uint32_t)(((kt*8 + ks*2 + bhi) ^ l7) << 4));
                    #pragma unroll
                    for (int i=0;i<2;i++){
                        mma16(acc[i][2*j2],   af[i], bq);
                        mma16(acc[i][2*j2+1], af[i], bq+2);
                    }
                }
            }
            buf ^= 1;
        }

        // epilogue for this m-block. c-frag: e0:(g,2t) e1:(g,2t+1) e2:(g+8,2t) e3:(g+8,2t+1)
        #pragma unroll
        for (int i=0;i<2;i++){
            const int r0 = mb*64 + wm + i*16 + g;
            #pragma unroll
            for (int j=0;j<8;j++){
                const int c0 = n0 + wn + j*8 + 2*t4;
                float v0 = acc[i][j][0] + bias[c0];
                float v1 = acc[i][j][1] + bias[c0+1];
                float v2 = acc[i][j][2] + bias[c0];
                float v3 = acc[i][j][3] + bias[c0+1];
                if (MODE == 0){
                    const int s  = c0 >> 9;
                    const int hh = (c0 >> 6) & 7;
                    const int d  = c0 & 63;
                    const int bq = r0 >> 6;
                    const int t  = r0 & 63;
                    const int off  = (((bq*8 + hh)*64 + t) << 6) + d;
                    const int off2 = off + (8 << 6);
                    if (s == 0){
                        *(half2*)&g_q[off]  = __floats2half2_rn(v0*0.125f, v1*0.125f);
                        *(half2*)&g_q[off2] = __floats2half2_rn(v2*0.125f, v3*0.125f);
                    } else if (s == 1){
                        *(half2*)&g_k[off]  = __floats2half2_rn(v0, v1);
                        *(half2*)&g_k[off2] = __floats2half2_rn(v2, v3);
                    } else {
                        *(half2*)&g_v[off]  = __floats2half2_rn(v0, v1);
                        *(half2*)&g_v[off2] = __floats2half2_rn(v2, v3);
                    }
                } else {
                    out[(size_t)r0*512 + c0]       = v0;
                    out[(size_t)r0*512 + c0 + 1]   = v1;
                    out[(size_t)(r0+8)*512 + c0]   = v2;
                    out[(size_t)(r0+8)*512 + c0+1] = v3;
                }
            }
        }
    }
}

// ---------------- fused attention per (window b, head h), fp16 ---------------
// 128 threads = 4 warps; warp w owns S/O rows [16w, 16w+16).
// Q/K row-major, V row-major (transposed in-flight via ldmatrix.trans).
// P aliases Q rows (warp-private). bias analytic from 225-entry slab.
#define SRH 72                                 // padded row stride (halfs)
#define ATTN_SMEM_BYTES (3*64*SRH*2 + 240*4)   // 28608 B
__global__ void __launch_bounds__(128)
attn_kernel(const float* __restrict__ btab, __half* __restrict__ attno)
{
    extern __shared__ uint8_t smem[];
    __half* sq = (__half*)smem;            // [64][72]; P overwrites in place
    __half* sk = sq + 64*SRH;
    __half* sv = sk + 64*SRH;              // V row-major [token][d]
    float*  sbias = (float*)(sv + 64*SRH);

    const int bh  = blockIdx.x;
    const int b   = bh >> 3;
    const int h   = bh & 7;
    const int lat = b >> 6;
    const int tid = threadIdx.x;
    const int lane = tid & 31;
    const int w   = tid >> 5;
    const int g   = lane >> 2;
    const int t4  = lane & 3;
    const int R0  = w * 16;

    const __half* qg = g_q + (size_t)bh * 4096;
    const __half* kg = g_k + (size_t)bh * 4096;
    const __half* vg = g_v + (size_t)bh * 4096;

    #pragma unroll
    for (int p=0;p<4;p++){
        const int idx = tid + p*128;        // 0..511
        const int row = idx >> 3;
        const int c8  = (idx & 7) * 8;
        *(uint4*)&sq[row*SRH + c8] = *(const uint4*)(qg + row*64 + c8);
        *(uint4*)&sk[row*SRH + c8] = *(const uint4*)(kg + row*64 + c8);
        *(uint4*)&sv[row*SRH + c8] = *(const uint4*)(vg + row*64 + c8);
    }
    for (int i = tid; i < PER_LAT; i += 128)
        sbias[i] = btab[(lat*PER_LAT + i)*8 + h];
    __syncthreads();

    const uint32_t sbase = (uint32_t)__cvta_generic_to_shared(smem);
    const uint32_t aAddr = sbase + 2u*(uint32_t)((R0 + (lane & 7) + ((lane >> 3) & 1)*8)*SRH
                                                 + ((lane >> 4) & 1)*8);
    const uint32_t kAddr = sbase + 2u*(uint32_t)(64*SRH + ((lane & 7) + ((lane >> 4) & 1)*8)*SRH
                                                 + ((lane >> 3) & 1)*8);
    const uint32_t vAddr = sbase + 2u*(uint32_t)(2*64*SRH + ((lane & 7) + ((lane >> 3) & 1)*8)*SRH
                                                 + ((lane >> 4) & 1)*8);
    const uint32_t JROW = 16*SRH*2;         // byte step: 16 rows

    // ---- S = (Q*scale) K^T ----
    float sacc[8][4];
    #pragma unroll
    for (int j=0;j<8;j++){ sacc[j][0]=0.f; sacc[j][1]=0.f; sacc[j][2]=0.f; sacc[j][3]=0.f; }
    #pragma unroll
    for (int ks=0; ks<4; ks++){
        uint32_t a[4];
        ldm_x4(a, aAddr + ks*32);
        #pragma unroll
        for (int j2=0;j2<4;j2++){
            uint32_t bq[4];
            ldm_x4(bq, kAddr + j2*JROW + ks*32);
            mma16(sacc[2*j2],   a, bq);
            mma16(sacc[2*j2+1], a, bq+2);
        }
    }

    // ---- bias + row softmax + write P (fp16) into sq (aliased) ----
    #pragma unroll
    for (int rr=0; rr<2; rr++){
        const int r   = R0 + g + rr*8;
        const int rR  = r >> 3, rC = r & 7;
        float tmp[16];
        float mx = -1e30f;
        #pragma unroll
        for (int j=0;j<8;j++){
            #pragma unroll
            for (int e=0;e<2;e++){
                const int c  = j*8 + 2*t4 + e;
                const int ib = (rR - (c>>3) + 7)*15 + (rC - (c&7) + 7);
                const float s = sacc[j][rr*2+e] + sbias[ib];
                tmp[j*2+e] = s;
                mx = fmaxf(mx, s);
            }
        }
        mx = fmaxf(mx, __shfl_xor_sync(0xffffffffu, mx, 1));
        mx = fmaxf(mx, __shfl_xor_sync(0xffffffffu, mx, 2));
        float sum = 0.f;
        #pragma unroll
        for (int i=0;i<16;i++){ tmp[i] = __expf(tmp[i]-mx); sum += tmp[i]; }
        sum += __shfl_xor_sync(0xffffffffu, sum, 1);
        sum += __shfl_xor_sync(0xffffffffu, sum, 2);
        const float rinv = 1.f / sum;
        #pragma unroll
        for (int j=0;j<8;j++)
            *(half2*)&sq[r*SRH + j*8 + 2*t4] =
                __floats2half2_rn(tmp[2*j]*rinv, tmp[2*j+1]*rinv);
    }
    __syncwarp();   // warp-private rows: P visible to own warp's ldmatrix

    // ---- O = P V (V transposed in-flight) ----
    float oacc[8][4];
    #pragma unroll
    for (int j=0;j<8;j++){ oacc[j][0]=0.f; oacc[j][1]=0.f; oacc[j][2]=0.f; oacc[j][3]=0.f; }
    #pragma unroll
    for (int ks=0; ks<4; ks++){             // k16 chunks over tokens
        uint32_t a[4];
        ldm_x4(a, aAddr + ks*32);           // P fragments (aliased sq)
        #pragma unroll
        for (int j2=0;j2<4;j2++){           // d16 groups
            uint32_t bq[4];
            ldm_x4t(bq, vAddr + ks*JROW + j2*32);
            mma16(oacc[2*j2],   a, bq);
            mma16(oacc[2*j2+1], a, bq+2);
        }
    }

    // write O fp16 -> attno[(b*64+r)*512 + h*64 + d]
    __half* ob = attno + (size_t)b * 64 * 512 + h * 64;
    #pragma unroll
    for (int j=0;j<8;j++){
        const int c0 = j*8 + 2*t4;
        const int r  = R0 + g;
        *(half2*)&ob[(size_t)r*512 + c0]     = __floats2half2_rn(oacc[j][0], oacc[j][1]);
        *(half2*)&ob[(size_t)(r+8)*512 + c0] = __floats2half2_rn(oacc[j][2], oacc[j][3]);
    }
}

// ---------------- launch -----------------------------------------------------
extern "C" void kernel_launch(void* const* d_in, const int* in_sizes, int n_in,
                              void* d_out, int out_size)
{
    const float* x     = (const float*)d_in[0];
    const float* wqkv  = (const float*)d_in[1];
    const float* bqkv  = (const float*)d_in[2];
    const float* wproj = (const float*)d_in[3];
    const float* bproj = (const float*)d_in[4];
    const float* btab  = (const float*)d_in[5];
    // d_in[6] = rel_idx: unused — computed analytically in-kernel.
    float* out = (float*)d_out;

    __half *gxh, *gwq, *gwp, *gao;
    cudaGetSymbolAddress((void**)&gxh, g_xh);
    cudaGetSymbolAddress((void**)&gwq, g_wq);
    cudaGetSymbolAddress((void**)&gwp, g_wp);
    cudaGetSymbolAddress((void**)&gao, g_ao);

    cudaFuncSetAttribute(gemm_f16<0>, cudaFuncAttributeMaxDynamicSharedMemorySize, GSMEM_BYTES);
    cudaFuncSetAttribute(gemm_f16<1>, cudaFuncAttributeMaxDynamicSharedMemorySize, GSMEM_BYTES);
    cudaFuncSetAttribute(attn_kernel, cudaFuncAttributeMaxDynamicSharedMemorySize, ATTN_SMEM_BYTES);

    // round all operands to fp16 (rn) in one pass
    round_all<<<8192, 256>>>(x, gxh, wqkv, gwq, wproj, gwp);

    // QKV GEMM: M=131072, N=1536, K=512 — persistent-B, 12 n-panels x 148 slots
    gemm_f16<0><<<dim3(12, 148), 256, GSMEM_BYTES>>>(gxh, gwq, bqkv, nullptr);
    // attention: one block per (window, head)
    attn_kernel<<<BWIN*HEADSC, 128, ATTN_SMEM_BYTES>>>(btab, gao);
    // projection GEMM: M=131072, N=512, K=512 — persistent-B, 4 n-panels x 148 slots
    gemm_f16<1><<<dim3(4, 148), 256, GSMEM_BYTES>>>(gao, gwp, bproj, out);
}

// round 17
// speedup vs baseline: 1.1239x; 1.1239x over previous
#include <cuda_runtime.h>
#include <cuda_fp16.h>
#include <cstdint>

// Problem constants
#define DIMC   512
#define HEADSC 8
#define NTOK   64          // tokens per window (8x8)
#define BWIN   2048        // number of windows (32*64)
#define MROWS  (BWIN*NTOK) // 131072
#define PER_LAT 225

// ---------------- scratch (static device memory; allocation is forbidden) ----
__device__ __half g_q [BWIN*HEADSC*NTOK*64]; // [B][H][N][D] fp16, q pre-scaled by 0.125
__device__ __half g_k [BWIN*HEADSC*NTOK*64];
__device__ __half g_v [BWIN*HEADSC*NTOK*64];
__device__ __half g_ao[(size_t)MROWS*DIMC];  // attention output fp16, [M,512]
__device__ __half g_xh[(size_t)MROWS*DIMC];  // x rounded to fp16
__device__ __half g_wq[3*DIMC*DIMC];         // w_qkv fp16
__device__ __half g_wp[DIMC*DIMC];           // w_proj fp16

// ---------------- helpers ----------------------------------------------------
__device__ __forceinline__ void mma16(float* c, const uint32_t* a, const uint32_t* b){
    asm volatile(
      "mma.sync.aligned.m16n8k16.row.col.f32.f16.f16.f32 "
      "{%0,%1,%2,%3}, {%4,%5,%6,%7}, {%8,%9}, {%0,%1,%2,%3};"
      : "+f"(c[0]), "+f"(c[1]), "+f"(c[2]), "+f"(c[3])
      : "r"(a[0]), "r"(a[1]), "r"(a[2]), "r"(a[3]), "r"(b[0]), "r"(b[1]));
}
__device__ __forceinline__ void ldm_x4(uint32_t* r, uint32_t addr){
    asm volatile("ldmatrix.sync.aligned.m8n8.x4.shared.b16 {%0,%1,%2,%3}, [%4];"
                 : "=r"(r[0]), "=r"(r[1]), "=r"(r[2]), "=r"(r[3]) : "r"(addr));
}
__device__ __forceinline__ void ldm_x4t(uint32_t* r, uint32_t addr){
    asm volatile("ldmatrix.sync.aligned.m8n8.x4.trans.shared.b16 {%0,%1,%2,%3}, [%4];"
                 : "=r"(r[0]), "=r"(r[1]), "=r"(r[2]), "=r"(r[3]) : "r"(addr));
}
__device__ __forceinline__ void cp16(uint32_t dst, const void* src){
    asm volatile("cp.async.cg.shared.global [%0], [%1], 16;\n" :: "r"(dst), "l"(src));
}
__device__ __forceinline__ void cp_commit(){ asm volatile("cp.async.commit_group;\n" ::); }
__device__ __forceinline__ uint32_t h2u(half2 h){ return *reinterpret_cast<uint32_t*>(&h); }

// ---------------- merged pre-round pass: fp16_rn of x, w_qkv, w_proj ---------
__global__ void round_all(const float* __restrict__ x,    __half* __restrict__ xh,
                          const float* __restrict__ wq,   __half* __restrict__ wqh,
                          const float* __restrict__ wp,   __half* __restrict__ wph)
{
    const int nx = (int)((size_t)MROWS*DIMC/4);
    const int nq = 3*DIMC*DIMC/4;
    const int np = DIMC*DIMC/4;
    const int total = nx + nq + np;
    int i = blockIdx.x * blockDim.x + threadIdx.x;
    const int stride = gridDim.x * blockDim.x;
    for (; i < total; i += stride){
        const float* s; __half* d; int k;
        if (i < nx){ s = x; d = xh; k = i; }
        else if (i < nx + nq){ s = wq; d = wqh; k = i - nx; }
        else { s = wp; d = wph; k = i - nx - nq; }
        float4 v = ((const float4*)s)[k];
        half2 h0 = __floats2half2_rn(v.x, v.y);
        half2 h1 = __floats2half2_rn(v.z, v.w);
        ((uint2*)d)[k] = make_uint2(h2u(h0), h2u(h1));
    }
}

// ---------------- fp16 GEMM: C[M,N] = A[M,K] * W[N,K]^T + bias[N] ------------
// MODE 0: epilogue -> q/k/v fp16 scatter (q scaled); MODE 1: -> f32 out.
// CTA tile 64(M)x128(N), 128 threads (4 warps as 2(M)x2(N), warp tile 32x64).
// ktile 64, 2-stage cp.async, XOR-swizzled compact stages (24.6 KB each) ->
// 49.2 KB/CTA, ~127 regs -> 4 CTAs/SM = 16 warps in 4 independent barrier
// domains. K=512 (8 ktiles).
// Swizzle: 16B chunk index c ^= (row & 7); identical on store & load since
// row&7 == lane&7 in every fragment map.
#define STG_BYTES ((64+128)*128)        // 24576
#define GSTAGES 2
#define GSMEM_BYTES (GSTAGES*STG_BYTES) // 49152

template<int MODE>
__global__ void __launch_bounds__(128)
gemm_f16(const __half* __restrict__ A, const __half* __restrict__ W,
         const float* __restrict__ bias, float* __restrict__ out)
{
    extern __shared__ uint8_t smem[];
    const uint32_t sbase = (uint32_t)__cvta_generic_to_shared(smem);

    const int tid  = threadIdx.x;
    const int lane = tid & 31;
    const int wid  = tid >> 5;
    const int n0   = blockIdx.x * 128;   // n fast: weight panels stay L2-resident
    const int m0   = blockIdx.y * 64;
    const int g    = lane >> 2;
    const int t4   = lane & 3;
    const int wm   = (wid & 1) * 32;     // M: 2 warps (32 rows each)
    const int wn   = (wid >> 1) * 64;    // N: 2 warps (64 cols each)

    const __half* Ag = A + (size_t)m0 * 512;
    const __half* Wg = W + (size_t)n0 * 512;

    // fragment lane geometry (low 3 bits of row == lane&7 always)
    const int l7   = lane & 7;
    const int ahi  = (lane >> 4) & 1;                   // A: chunk-half selector
    const int arow = wm + l7 + ((lane >> 3) & 1) * 8;   // + i*16 at use
    const int bhi  = (lane >> 3) & 1;                   // B: chunk-half selector
    const int brow = 64 + wn + l7 + ((lane >> 4) & 1) * 8;   // + j2*16 at use

    const uint32_t arow_b = (uint32_t)arow * 128;
    const uint32_t brow_b = (uint32_t)brow * 128;

    float acc[2][8][4];
    #pragma unroll
    for (int i=0;i<2;i++)
      #pragma unroll
      for (int j=0;j<8;j++)
        #pragma unroll
        for (int e=0;e<4;e++) acc[i][j][e] = 0.f;

    // staging: 1536 16B chunks per ktile (A 512, B 1024), 12 per thread
    auto issue = [&](int kt, int stage){
        const uint32_t so_base = sbase + (uint32_t)stage * STG_BYTES;
        #pragma unroll
        for (int p=0;p<12;p++){
            const int c = p*128 + tid;          // 0..1535
            int row, chunk;
            const __half* gp;
            if (p < 4){                         // A: stage rows 0..63
                row   = c >> 3;
                chunk = c & 7;
                gp    = Ag + (size_t)row*512 + kt*64 + chunk*8;
            } else {                            // B: stage rows 64..191
                const int cb = c - 512;
                const int n  = cb >> 3;
                chunk = cb & 7;
                gp    = Wg + (size_t)n*512 + kt*64 + chunk*8;
                row   = 64 + n;
            }
            const uint32_t dst = so_base + (uint32_t)row*128
                               + (uint32_t)((chunk ^ (row & 7)) << 4);
            cp16(dst, gp);
        }
        cp_commit();
    };

    issue(0, 0);

    for (int kt = 0; kt < 8; kt++){
        __syncthreads();                               // all done compute(kt-1): stage (kt+1)&1 free
        if (kt + 1 < 8) issue(kt + 1, (kt + 1) & 1);
        else            cp_commit();                   // uniform FIFO
        asm volatile("cp.async.wait_group 1;\n" ::);   // stage kt arrived (kt+1 may fly)
        __syncthreads();                               // stage kt visible to all

        const uint32_t sA = sbase + (uint32_t)(kt & 1) * STG_BYTES;
        #pragma unroll
        for (int ks=0; ks<4; ks++){                    // k16 chunks
            uint32_t af[2][4];
            #pragma unroll
            for (int i=0;i<2;i++)
                ldm_x4(af[i], sA + arow_b + (uint32_t)(i*16*128)
                             + (uint32_t)((((ks*2 + ahi) ^ l7)) << 4));
            #pragma unroll
            for (int j2=0;j2<4;j2++){
                uint32_t bq[4];
                ldm_x4(bq, sA + brow_b + (uint32_t)(j2*16*128)
                          + (uint32_t)((((ks*2 + bhi) ^ l7)) << 4));
                #pragma unroll
                for (int i=0;i<2;i++){
                    mma16(acc[i][2*j2],   af[i], bq);
                    mma16(acc[i][2*j2+1], af[i], bq+2);
                }
            }
        }
    }

    // epilogue. c-frag: e0:(g,2t) e1:(g,2t+1) e2:(g+8,2t) e3:(g+8,2t+1)
    #pragma unroll
    for (int i=0;i<2;i++){
        const int r0 = m0 + wm + i*16 + g;
        #pragma unroll
        for (int j=0;j<8;j++){
            const int c0 = n0 + wn + j*8 + 2*t4;      // even
            float v0 = acc[i][j][0] + bias[c0];
            float v1 = acc[i][j][1] + bias[c0+1];
            float v2 = acc[i][j][2] + bias[c0];
            float v3 = acc[i][j][3] + bias[c0+1];
            if (MODE == 0){
                const int s  = c0 >> 9;
                const int hh = (c0 >> 6) & 7;
                const int d  = c0 & 63;
                const int bq = r0 >> 6;
                const int t  = r0 & 63;
                const int off  = (((bq*8 + hh)*64 + t) << 6) + d;
                const int off2 = off + (8 << 6);      // row +8, same window
                if (s == 0){
                    *(half2*)&g_q[off]  = __floats2half2_rn(v0*0.125f, v1*0.125f);
                    *(half2*)&g_q[off2] = __floats2half2_rn(v2*0.125f, v3*0.125f);
                } else if (s == 1){
                    *(half2*)&g_k[off]  = __floats2half2_rn(v0, v1);
                    *(half2*)&g_k[off2] = __floats2half2_rn(v2, v3);
                } else {
                    *(half2*)&g_v[off]  = __floats2half2_rn(v0, v1);
                    *(half2*)&g_v[off2] = __floats2half2_rn(v2, v3);
                }
            } else {
                out[(size_t)r0*512 + c0]       = v0;
                out[(size_t)r0*512 + c0 + 1]   = v1;
                out[(size_t)(r0+8)*512 + c0]   = v2;
                out[(size_t)(r0+8)*512 + c0+1] = v3;
            }
        }
    }
}

// ---------------- fused attention per (window b, head h), fp16 ---------------
// 128 threads = 4 warps; warp w owns S/O rows [16w, 16w+16).
// Q/K row-major, V row-major (transposed in-flight via ldmatrix.trans).
// P aliases Q rows (warp-private). bias analytic from 225-entry slab.
// Staging via cp.async (no LDG->RF->STS round-trip).
#define SRH 72                                 // padded row stride (halfs)
#define ATTN_SMEM_BYTES (3*64*SRH*2 + 240*4)   // 28608 B
__global__ void __launch_bounds__(128)
attn_kernel(const float* __restrict__ btab, __half* __restrict__ attno)
{
    extern __shared__ uint8_t smem[];
    __half* sq = (__half*)smem;            // [64][72]; P overwrites in place
    float*  sbias = (float*)(smem + 3*64*SRH*2);

    const int bh  = blockIdx.x;
    const int b   = bh >> 3;
    const int h   = bh & 7;
    const int lat = b >> 6;
    const int tid = threadIdx.x;
    const int lane = tid & 31;
    const int w   = tid >> 5;
    const int g   = lane >> 2;
    const int t4  = lane & 3;
    const int R0  = w * 16;

    const __half* qg = g_q + (size_t)bh * 4096;

    const uint32_t sbase = (uint32_t)__cvta_generic_to_shared(smem);

    // stage q/k/v via cp.async: 3 buffers x 512 chunks of 16B; 12 per thread.
    // buffer order q,k,v matches g_q/g_k/g_v layout (each 4096 halfs apart in
    // separate arrays; use per-array base).
    {
        // q
        #pragma unroll
        for (int p=0;p<4;p++){
            const int idx = tid + p*128;        // 0..511
            const int row = idx >> 3;
            const int c8  = idx & 7;
            cp16(sbase + (uint32_t)(row*SRH + c8*8)*2, qg + row*64 + c8*8);
        }
        const __half* kg = g_k + (size_t)bh * 4096;
        #pragma unroll
        for (int p=0;p<4;p++){
            const int idx = tid + p*128;
            const int row = idx >> 3;
            const int c8  = idx & 7;
            cp16(sbase + (uint32_t)(64*SRH + row*SRH + c8*8)*2, kg + row*64 + c8*8);
        }
        const __half* vg = g_v + (size_t)bh * 4096;
        #pragma unroll
        for (int p=0;p<4;p++){
            const int idx = tid + p*128;
            const int row = idx >> 3;
            const int c8  = idx & 7;
            cp16(sbase + (uint32_t)(2*64*SRH + row*SRH + c8*8)*2, vg + row*64 + c8*8);
        }
        cp_commit();
    }
    // bias slab via regular loads (overlaps with cp.async in flight)
    for (int i = tid; i < PER_LAT; i += 128)
        sbias[i] = btab[(lat*PER_LAT + i)*8 + h];
    asm volatile("cp.async.wait_group 0;\n" ::);
    __syncthreads();

    const uint32_t aAddr = sbase + 2u*(uint32_t)((R0 + (lane & 7) + ((lane >> 3) & 1)*8)*SRH
                                                 + ((lane >> 4) & 1)*8);
    const uint32_t kAddr = sbase + 2u*(uint32_t)(64*SRH + ((lane & 7) + ((lane >> 4) & 1)*8)*SRH
                                                 + ((lane >> 3) & 1)*8);
    const uint32_t vAddr = sbase + 2u*(uint32_t)(2*64*SRH + ((lane & 7) + ((lane >> 3) & 1)*8)*SRH
                                                 + ((lane >> 4) & 1)*8);
    const uint32_t JROW = 16*SRH*2;         // byte step: 16 rows

    // ---- S = (Q*scale) K^T ----
    float sacc[8][4];
    #pragma unroll
    for (int j=0;j<8;j++){ sacc[j][0]=0.f; sacc[j][1]=0.f; sacc[j][2]=0.f; sacc[j][3]=0.f; }
    #pragma unroll
    for (int ks=0; ks<4; ks++){
        uint32_t a[4];
        ldm_x4(a, aAddr + ks*32);
        #pragma unroll
        for (int j2=0;j2<4;j2++){
            uint32_t bq[4];
            ldm_x4(bq, kAddr + j2*JROW + ks*32);
            mma16(sacc[2*j2],   a, bq);
            mma16(sacc[2*j2+1], a, bq+2);
        }
    }

    // ---- bias + row softmax + write P (fp16) into sq (aliased) ----
    #pragma unroll
    for (int rr=0; rr<2; rr++){
        const int r   = R0 + g + rr*8;
        const int rR  = r >> 3, rC = r & 7;
        float tmp[16];
        float mx = -1e30f;
        #pragma unroll
        for (int j=0;j<8;j++){
            #pragma unroll
            for (int e=0;e<2;e++){
                const int c  = j*8 + 2*t4 + e;
                const int ib = (rR - (c>>3) + 7)*15 + (rC - (c&7) + 7);
                const float s = sacc[j][rr*2+e] + sbias[ib];
                tmp[j*2+e] = s;
                mx = fmaxf(mx, s);
            }
        }
        mx = fmaxf(mx, __shfl_xor_sync(0xffffffffu, mx, 1));
        mx = fmaxf(mx, __shfl_xor_sync(0xffffffffu, mx, 2));
        float sum = 0.f;
        #pragma unroll
        for (int i=0;i<16;i++){ tmp[i] = __expf(tmp[i]-mx); sum += tmp[i]; }
        sum += __shfl_xor_sync(0xffffffffu, sum, 1);
        sum += __shfl_xor_sync(0xffffffffu, sum, 2);
        const float rinv = 1.f / sum;
        #pragma unroll
        for (int j=0;j<8;j++)
            *(half2*)&sq[r*SRH + j*8 + 2*t4] =
                __floats2half2_rn(tmp[2*j]*rinv, tmp[2*j+1]*rinv);
    }
    __syncwarp();   // warp-private rows: P visible to own warp's ldmatrix

    // ---- O = P V (V transposed in-flight) ----
    float oacc[8][4];
    #pragma unroll
    for (int j=0;j<8;j++){ oacc[j][0]=0.f; oacc[j][1]=0.f; oacc[j][2]=0.f; oacc[j][3]=0.f; }
    #pragma unroll
    for (int ks=0; ks<4; ks++){             // k16 chunks over tokens
        uint32_t a[4];
        ldm_x4(a, aAddr + ks*32);           // P fragments (aliased sq)
        #pragma unroll
        for (int j2=0;j2<4;j2++){           // d16 groups
            uint32_t bq[4];
            ldm_x4t(bq, vAddr + ks*JROW + j2*32);
            mma16(oacc[2*j2],   a, bq);
            mma16(oacc[2*j2+1], a, bq+2);
        }
    }

    // write O fp16 -> attno[(b*64+r)*512 + h*64 + d]
    __half* ob = attno + (size_t)b * 64 * 512 + h * 64;
    #pragma unroll
    for (int j=0;j<8;j++){
        const int c0 = j*8 + 2*t4;
        const int r  = R0 + g;
        *(half2*)&ob[(size_t)r*512 + c0]     = __floats2half2_rn(oacc[j][0], oacc[j][1]);
        *(half2*)&ob[(size_t)(r+8)*512 + c0] = __floats2half2_rn(oacc[j][2], oacc[j][3]);
    }
}

// ---------------- launch -----------------------------------------------------
extern "C" void kernel_launch(void* const* d_in, const int* in_sizes, int n_in,
                              void* d_out, int out_size)
{
    const float* x     = (const float*)d_in[0];
    const float* wqkv  = (const float*)d_in[1];
    const float* bqkv  = (const float*)d_in[2];
    const float* wproj = (const float*)d_in[3];
    const float* bproj = (const float*)d_in[4];
    const float* btab  = (const float*)d_in[5];
    // d_in[6] = rel_idx: unused — computed analytically in-kernel.
    float* out = (float*)d_out;

    __half *gxh, *gwq, *gwp, *gao;
    cudaGetSymbolAddress((void**)&gxh, g_xh);
    cudaGetSymbolAddress((void**)&gwq, g_wq);
    cudaGetSymbolAddress((void**)&gwp, g_wp);
    cudaGetSymbolAddress((void**)&gao, g_ao);

    cudaFuncSetAttribute(gemm_f16<0>, cudaFuncAttributeMaxDynamicSharedMemorySize, GSMEM_BYTES);
    cudaFuncSetAttribute(gemm_f16<1>, cudaFuncAttributeMaxDynamicSharedMemorySize, GSMEM_BYTES);
    cudaFuncSetAttribute(attn_kernel, cudaFuncAttributeMaxDynamicSharedMemorySize, ATTN_SMEM_BYTES);

    // round all operands to fp16 (rn) in one pass
    round_all<<<8192, 256>>>(x, gxh, wqkv, gwq, wproj, gwp);

    // QKV GEMM: M=131072, N=1536, K=512
    gemm_f16<0><<<dim3(12, 2048), 128, GSMEM_BYTES>>>(gxh, gwq, bqkv, nullptr);
    // attention: one block per (window, head)
    attn_kernel<<<BWIN*HEADSC, 128, ATTN_SMEM_BYTES>>>(btab, gao);
    // projection GEMM: M=131072, N=512, K=512
    gemm_f16<1><<<dim3(4, 2048), 128, GSMEM_BYTES>>>(gao, gwp, bproj, out);
}